// round 11
// baseline (speedup 1.0000x reference)
#include <cuda_runtime.h>
#include <cuda_bf16.h>
#include <math.h>
#include <stdint.h>

#define EPSQ 1e-5f
#define QBF  127.0f

#define S_LEN 2048
#define D_DIM 2048
#define P_DIM 16
#define HEADS 16
#define HD    128
#define BATCH 2
#define NTOK  (BATCH * S_LEN)
#define BHTOT (BATCH * HEADS)

// ---------------- scratch ----------------
__device__ __nv_bfloat16 g_proj[3][(size_t)BHTOT * S_LEN * HD];   // q(*log2e/sqrt(hd)),k,v
__device__ int4  g_wq[6][2048];
__device__ float g_wscale[6];
__device__ float g_winv[6];

// ---------------- weight scale (reduce only) ----------------
__global__ __launch_bounds__(1024) void quant_scale_kernel(
        const float* __restrict__ w0, const float* __restrict__ w1,
        const float* __restrict__ w2, const float* __restrict__ w3,
        const float* __restrict__ w4, const float* __restrict__ w5) {
    const float* ws[6] = {w0, w1, w2, w3, w4, w5};
    const int j = blockIdx.x;
    const float* w = ws[j];
    const int N = P_DIM * D_DIM;
    int tid = threadIdx.x;

    float sum = 0.f;
    for (int i = tid; i < N; i += 1024) sum += fabsf(w[i]);
    #pragma unroll
    for (int o = 16; o > 0; o >>= 1) sum += __shfl_xor_sync(0xffffffffu, sum, o);
    __shared__ float red[32];
    if ((tid & 31) == 0) red[tid >> 5] = sum;
    __syncthreads();
    if (tid == 0) {
        float t = 0.f;
        for (int k = 0; k < 32; k++) t += red[k];
        float sc = fmaxf(t / (float)N, EPSQ);
        g_wscale[j] = sc;
        g_winv[j] = 1.0f / sc;
    }
}

// ---------------- weight quantize ----------------
__global__ __launch_bounds__(256) void quant_pack_kernel(
        const float* __restrict__ w0, const float* __restrict__ w1,
        const float* __restrict__ w2, const float* __restrict__ w3,
        const float* __restrict__ w4, const float* __restrict__ w5) {
    const float* ws[6] = {w0, w1, w2, w3, w4, w5};
    const int j = blockIdx.y;
    const float* w = ws[j] + blockIdx.x * 4096;
    char* out = (char*)g_wq[j] + blockIdx.x * 4096;
    const float wsv = g_winv[j];
    int tid = threadIdx.x;
    #pragma unroll
    for (int u = 0; u < 4; u++) {
        int base = (tid + u * 256) * 4;
        float4 v = *(const float4*)(w + base);
        char4 q;
        float a;
        a = fminf(fmaxf(rintf(v.x * wsv), -1.f), 1.f); q.x = (char)(int)a;
        a = fminf(fmaxf(rintf(v.y * wsv), -1.f), 1.f); q.y = (char)(int)a;
        a = fminf(fmaxf(rintf(v.z * wsv), -1.f), 1.f); q.z = (char)(int)a;
        a = fminf(fmaxf(rintf(v.w * wsv), -1.f), 1.f); q.w = (char)(int)a;
        *(char4*)(out + base) = q;
    }
}

// ---------------- fused projection: one block per token, all 3 matrices ----------------
__global__ __launch_bounds__(256) void proj_kernel(const float* __restrict__ x) {
    const int t = blockIdx.x;
    const int b = t >> 11;
    const int s = t & 2047;
    const int tid = threadIdx.x;

    __shared__ float xs[D_DIM];
    __shared__ int   xq[D_DIM / 4];
    __shared__ int   redi[8 * 16];
    __shared__ float rmax[8];
    __shared__ float s_cmax;
    __shared__ int   aqp[3][4];
    __shared__ float fct[3];

    const float* xr = x + (size_t)t * D_DIM;
    float mx = 0.f;
    for (int i = tid; i < D_DIM / 4; i += 256) {
        float4 v = ((const float4*)xr)[i];
        ((float4*)xs)[i] = v;
        mx = fmaxf(mx, fmaxf(fmaxf(fabsf(v.x), fabsf(v.y)), fmaxf(fabsf(v.z), fabsf(v.w))));
    }
    #pragma unroll
    for (int o = 16; o > 0; o >>= 1) mx = fmaxf(mx, __shfl_xor_sync(0xffffffffu, mx, o));
    if ((tid & 31) == 0) rmax[tid >> 5] = mx;
    __syncthreads();
    if (tid == 0) {
        float mm = rmax[0];
        for (int k = 1; k < 8; k++) mm = fmaxf(mm, rmax[k]);
        s_cmax = fmaxf(mm, EPSQ);
    }
    __syncthreads();
    const float cmax = s_cmax;
    const float sx = QBF / cmax;

    {
        int base = tid * 8;
        #pragma unroll
        for (int g = 0; g < 2; g++) {
            int v = 0;
            #pragma unroll
            for (int u = 0; u < 4; u++) {
                float q = rintf(xs[base + g * 4 + u] * sx);
                q = fminf(fmaxf(q, -128.f), 127.f);
                v |= (((int)q) & 0xFF) << (8 * u);
            }
            xq[tid * 2 + g] = v;
        }
    }
    __syncthreads();

    const int x0 = xq[tid * 2 + 0];
    const int x1 = xq[tid * 2 + 1];

    #pragma unroll 1
    for (int m = 0; m < 3; m++) {
        const int* wmat = (const int*)g_wq[2 * m];
        int acc[16];
        #pragma unroll
        for (int p = 0; p < 16; p++) {
            const int* wp = wmat + p * 512;
            int a = __dp4a(x0, wp[tid * 2 + 0], 0);
            a = __dp4a(x1, wp[tid * 2 + 1], a);
            acc[p] = a;
        }
        #pragma unroll
        for (int p = 0; p < 16; p++) acc[p] = __reduce_add_sync(0xffffffffu, acc[p]);
        if ((tid & 31) == 0) {
            #pragma unroll
            for (int p = 0; p < 16; p++) redi[(tid >> 5) * 16 + p] = acc[p];
        }
        __syncthreads();
        if (tid < 16) {
            int tot = 0;
            #pragma unroll
            for (int w = 0; w < 8; w++) tot += redi[w * 16 + tid];
            float a = (float)tot * (cmax / QBF) * g_wscale[2 * m];
            float h = 0.5f * a * (1.0f + erff(a * 0.70710678118654752f));
            float ss = h * h;
            #pragma unroll
            for (int o = 8; o > 0; o >>= 1) ss += __shfl_xor_sync(0x0000ffffu, ss, o, 16);
            float nrm = fmaxf(sqrtf(ss), 1e-12f);
            h = h / nrm * 4.0f;
            float am = fabsf(h);
            #pragma unroll
            for (int o = 8; o > 0; o >>= 1) am = fmaxf(am, __shfl_xor_sync(0x0000ffffu, am, o, 16));
            am = fmaxf(am, EPSQ);
            float sa = QBF / am;
            float q = fminf(fmaxf(rintf(h * sa), -128.f), 127.f);
            ((char*)&aqp[m][0])[tid] = (char)(int)q;
            if (tid == 0) {
                float f = (am / QBF) * g_wscale[2 * m + 1];
                if (m == 0) f *= 0.08838834764831845f * 1.4426950408889634f; // 1/sqrt(hd)*log2(e)
                fct[m] = f;
            }
        }
        __syncthreads();
    }

    #pragma unroll
    for (int j = 0; j < 8; j++) {
        int d = tid + 256 * j;
        int h = d >> 7, dh = d & 127;
        size_t oidx = ((size_t)(b * HEADS + h) * S_LEN + s) * HD + dh;
        #pragma unroll
        for (int m = 0; m < 3; m++) {
            const int4 wv = g_wq[2 * m + 1][d];
            int acc = __dp4a(aqp[m][0], wv.x, 0);
            acc = __dp4a(aqp[m][1], wv.y, acc);
            acc = __dp4a(aqp[m][2], wv.z, acc);
            acc = __dp4a(aqp[m][3], wv.w, acc);
            g_proj[m][oidx] = __float2bfloat16((float)acc * fct[m]);
        }
    }
}

// ============ warp-specialized flash attention (512 threads) ============
// warps 0-7 (A): S = Q K^T, online softmax, P -> smem, own m/l
// warps 8-15 (B): O rescale + O += P V (V via ldmatrix.trans), cp.async copies, output
#define KLDB  272                    // bytes per K/V smem row (128 bf16 + 16B pad)
#define KLD2  68                     // words per row
#define KTILE (64 * KLDB)            // 17408
#define STAGEB (2 * KTILE)           // 34816 (K + V)
#define NST   3
#define P_OFF (NST * STAGEB)         // 104448
#define PLDB  144                    // P row stride bytes (64 bf16 + pad)
#define PBUF  (128 * PLDB)           // 18432
#define C_OFF (P_OFF + 2 * PBUF)     // 141312
#define L_OFF (C_OFF + 2 * 512)      // 142336
#define ATTN_SMEM_BYTES (L_OFF + 512)   // 142848

// named barriers: KR0=1 KR1=7 (stage ready), PF0=2 PF1=3 (P full), PE0=4 PE1=5 (P empty),
//                 FIN=6, BGRP=8 (B-group internal, count 256)
#define BAR_SYNC(id)    asm volatile("bar.sync %0, 512;"   :: "r"(id) : "memory")
#define BAR_ARRIVE(id)  asm volatile("bar.arrive %0, 512;" :: "r"(id) : "memory")
#define BAR_SYNC_B(id)  asm volatile("bar.sync %0, 256;"   :: "r"(id) : "memory")

__device__ __forceinline__ void mma_bf16(float* d, const uint32_t* a, const uint32_t b0, const uint32_t b1) {
    asm volatile("mma.sync.aligned.m16n8k16.row.col.f32.bf16.bf16.f32 "
        "{%0,%1,%2,%3}, {%4,%5,%6,%7}, {%8,%9}, {%0,%1,%2,%3};"
        : "+f"(d[0]), "+f"(d[1]), "+f"(d[2]), "+f"(d[3])
        : "r"(a[0]), "r"(a[1]), "r"(a[2]), "r"(a[3]), "r"(b0), "r"(b1));
}
__device__ __forceinline__ void ldsm4(uint32_t& r0, uint32_t& r1, uint32_t& r2, uint32_t& r3, uint32_t addr) {
    asm volatile("ldmatrix.sync.aligned.m8n8.x4.shared.b16 {%0,%1,%2,%3}, [%4];"
        : "=r"(r0), "=r"(r1), "=r"(r2), "=r"(r3) : "r"(addr));
}
__device__ __forceinline__ void ldsm4t(uint32_t& r0, uint32_t& r1, uint32_t& r2, uint32_t& r3, uint32_t addr) {
    asm volatile("ldmatrix.sync.aligned.m8n8.x4.trans.shared.b16 {%0,%1,%2,%3}, [%4];"
        : "=r"(r0), "=r"(r1), "=r"(r2), "=r"(r3) : "r"(addr));
}
__device__ __forceinline__ uint32_t packbf(float hi, float lo) {
    uint32_t d;
    asm("cvt.rn.bf16x2.f32 %0, %1, %2;" : "=r"(d) : "f"(hi), "f"(lo));
    return d;
}
__device__ __forceinline__ float ex2(float x) {
    float y;
    asm("ex2.approx.f32 %0, %1;" : "=f"(y) : "f"(x));
    return y;
}
__device__ __forceinline__ void cpa16(uint32_t dst, const void* src) {
    asm volatile("cp.async.cg.shared.global [%0], [%1], 16;" :: "r"(dst), "l"(src));
}
__device__ __forceinline__ void cpa_commit() {
    asm volatile("cp.async.commit_group;" ::: "memory");
}
template<int N> __device__ __forceinline__ void cpa_wait() {
    asm volatile("cp.async.wait_group %0;" :: "n"(N) : "memory");
}
__device__ __forceinline__ void sts32(uint32_t addr, uint32_t v) {
    asm volatile("st.shared.b32 [%0], %1;" :: "r"(addr), "r"(v) : "memory");
}

__global__ __launch_bounds__(512, 1) void attn_kernel(float* __restrict__ out) {
    extern __shared__ char sm[];
    const int bh = blockIdx.y;
    const int q0 = blockIdx.x * 128;
    const int tid = threadIdx.x;
    const int w = tid >> 5;
    const int lane = tid & 31;
    const int g = lane >> 2;
    const int t = lane & 3;
    const uint32_t smb = (uint32_t)__cvta_generic_to_shared(sm);

    // -------- stage Q (all 512 threads), A builds fragments --------
    {
        const __nv_bfloat16* qb = g_proj[0] + ((size_t)bh * S_LEN + q0) * HD;
        uint4* smq = (uint4*)sm;
        for (int i = tid; i < 128 * 16; i += 512) {
            int r = i >> 4, c = i & 15;
            smq[r * 17 + c] = ((const uint4*)(qb + (size_t)r * HD))[c];
        }
    }
    __syncthreads();

    if (w < 8) {
        // =================== GROUP A: S + softmax ===================
        uint32_t qa[8][4];
        {
            const uint32_t* Q = (const uint32_t*)sm;
            const int r0 = (16 * w + g) * KLD2;
            const int r1 = r0 + 8 * KLD2;
            #pragma unroll
            for (int kk = 0; kk < 8; kk++) {
                int c = kk * 8 + t;
                qa[kk][0] = Q[r0 + c];
                qa[kk][1] = Q[r1 + c];
                qa[kk][2] = Q[r0 + c + 4];
                qa[kk][3] = Q[r1 + c + 4];
            }
        }
        __syncthreads();   // Q area free for copies

        const int lr = lane & 7;
        const int kh = (lane >> 3) & 1;
        const int nh = (lane >> 4) & 1;
        uint32_t koff[4];
        #pragma unroll
        for (int ntp = 0; ntp < 4; ntp++)
            koff[ntp] = (uint32_t)((16 * ntp + 8 * nh + lr) * KLDB + kh * 16);

        float m0 = -INFINITY, m1 = -INFINITY, l0 = 0.f, l1 = 0.f;
        const int prow0 = 16 * w + g;

        #pragma unroll 1
        for (int jt = 0; jt < 32; jt++) {
            BAR_SYNC((jt & 1) ? 7 : 1);          // stage jt ready

            float s[8][4];
            #pragma unroll
            for (int nt = 0; nt < 8; nt++) { s[nt][0] = 0.f; s[nt][1] = 0.f; s[nt][2] = 0.f; s[nt][3] = 0.f; }
            const uint32_t kb = smb + (jt % 3) * STAGEB;
            #pragma unroll
            for (int kk = 0; kk < 8; kk++) {
                #pragma unroll
                for (int ntp = 0; ntp < 4; ntp++) {
                    uint32_t r0, r1, r2, r3;
                    ldsm4(r0, r1, r2, r3, kb + koff[ntp] + kk * 32);
                    mma_bf16(s[2 * ntp], qa[kk], r0, r1);
                    mma_bf16(s[2 * ntp + 1], qa[kk], r2, r3);
                }
            }

            // online softmax
            float mt0 = -INFINITY, mt1 = -INFINITY;
            #pragma unroll
            for (int nt = 0; nt < 8; nt++) {
                mt0 = fmaxf(mt0, fmaxf(s[nt][0], s[nt][1]));
                mt1 = fmaxf(mt1, fmaxf(s[nt][2], s[nt][3]));
            }
            mt0 = fmaxf(mt0, __shfl_xor_sync(0xffffffffu, mt0, 1));
            mt0 = fmaxf(mt0, __shfl_xor_sync(0xffffffffu, mt0, 2));
            mt1 = fmaxf(mt1, __shfl_xor_sync(0xffffffffu, mt1, 1));
            mt1 = fmaxf(mt1, __shfl_xor_sync(0xffffffffu, mt1, 2));
            float mn0 = fmaxf(m0, mt0), mn1 = fmaxf(m1, mt1);
            float c0 = ex2(m0 - mn0), c1 = ex2(m1 - mn1);
            m0 = mn0; m1 = mn1;
            float rs0 = 0.f, rs1 = 0.f;
            #pragma unroll
            for (int nt = 0; nt < 8; nt++) {
                s[nt][0] = ex2(s[nt][0] - mn0);
                s[nt][1] = ex2(s[nt][1] - mn0);
                s[nt][2] = ex2(s[nt][2] - mn1);
                s[nt][3] = ex2(s[nt][3] - mn1);
                rs0 += s[nt][0] + s[nt][1];
                rs1 += s[nt][2] + s[nt][3];
            }
            rs0 += __shfl_xor_sync(0xffffffffu, rs0, 1);
            rs0 += __shfl_xor_sync(0xffffffffu, rs0, 2);
            rs1 += __shfl_xor_sync(0xffffffffu, rs1, 1);
            rs1 += __shfl_xor_sync(0xffffffffu, rs1, 2);
            l0 = l0 * c0 + rs0;    // l0 holds FULL row sum per lane
            l1 = l1 * c1 + rs1;

            if (jt >= 2) BAR_SYNC(4 + (jt & 1));   // P buffer empty

            // write P (bf16) and c to smem
            const uint32_t pb = smb + P_OFF + (jt & 1) * PBUF;
            const uint32_t a0 = pb + prow0 * PLDB + (2 * t) * 2;
            const uint32_t a1 = a0 + 8 * PLDB;
            #pragma unroll
            for (int nt = 0; nt < 8; nt++) {
                sts32(a0 + nt * 16, packbf(s[nt][1], s[nt][0]));
                sts32(a1 + nt * 16, packbf(s[nt][3], s[nt][2]));
            }
            if (t == 0) {
                uint32_t ca = smb + C_OFF + (jt & 1) * 512 + prow0 * 4;
                sts32(ca, __float_as_uint(c0));
                sts32(ca + 32, __float_as_uint(c1));
            }
            BAR_ARRIVE(2 + (jt & 1));              // P full
        }

        // final l to smem (each lane already holds the full row sum — NO further reduction)
        if (t == 0) {
            uint32_t la = smb + L_OFF + prow0 * 4;
            sts32(la, __float_as_uint(l0));
            sts32(la + 32, __float_as_uint(l1));
        }
        BAR_ARRIVE(6);
    } else {
        // =================== GROUP B: PV + copies + output ===================
        __syncthreads();   // pair with A's second syncthreads

        const int wb = w - 8;
        const int btid = tid - 256;
        const int lr = lane & 7;
        const int kr8 = 8 * ((lane >> 3) & 1);
        const int nh8 = 8 * ((lane >> 4) & 1);

        const __nv_bfloat16* kbase = g_proj[1] + (size_t)bh * S_LEN * HD;
        const __nv_bfloat16* vbase = g_proj[2] + (size_t)bh * S_LEN * HD;

        auto copy_tile = [&](int jt) {
            const uint32_t base = smb + (jt % 3) * STAGEB;
            const __nv_bfloat16* kb = kbase + (size_t)jt * 64 * HD;
            const __nv_bfloat16* vb = vbase + (size_t)jt * 64 * HD;
            #pragma unroll
            for (int u = 0; u < 4; u++) {
                int i = btid + u * 256;
                int r = i >> 4, c = i & 15;
                cpa16(base + r * KLDB + c * 16, kb + r * HD + c * 8);
                cpa16(base + KTILE + r * KLDB + c * 16, vb + r * HD + c * 8);
            }
        };

        copy_tile(0); cpa_commit();
        copy_tile(1); cpa_commit();
        copy_tile(2); cpa_commit();
        cpa_wait<2>();                 // tile 0 resident
        BAR_ARRIVE(1);                 // KR for stage 0 (A iter 0)

        float o[16][4];
        #pragma unroll
        for (int nt = 0; nt < 16; nt++) { o[nt][0] = 0.f; o[nt][1] = 0.f; o[nt][2] = 0.f; o[nt][3] = 0.f; }

        // P ldmatrix address (A-operand frags)
        const uint32_t prow = (uint32_t)(16 * wb + lr + kr8);
        const uint32_t pcol = (uint32_t)(16 * ((lane >> 4) & 1));

        #pragma unroll 1
        for (int jt = 0; jt < 32; jt++) {
            cpa_wait<1>();                              // tile jt+1 resident
            if (jt < 31) BAR_ARRIVE((jt & 1) ? 1 : 7);  // KR for stage jt+1

            BAR_SYNC(2 + (jt & 1));                     // P(jt) full

            // load P A-frags + c
            const uint32_t pb = smb + P_OFF + (jt & 1) * PBUF;
            uint32_t pa[4][4];
            #pragma unroll
            for (int kk2 = 0; kk2 < 4; kk2++)
                ldsm4(pa[kk2][0], pa[kk2][1], pa[kk2][2], pa[kk2][3],
                      pb + prow * PLDB + kk2 * 32 + pcol);
            float c0 = *(const float*)(sm + C_OFF + (jt & 1) * 512 + (16 * wb + g) * 4);
            float c1 = *(const float*)(sm + C_OFF + (jt & 1) * 512 + (16 * wb + g + 8) * 4);

            if (jt < 30) BAR_ARRIVE(4 + (jt & 1));      // P(jt) consumed

            #pragma unroll
            for (int nt = 0; nt < 16; nt++) {
                o[nt][0] *= c0; o[nt][1] *= c0;
                o[nt][2] *= c1; o[nt][3] *= c1;
            }

            // PV: V via trans-ldmatrix from natural [key][hd] layout
            const uint32_t vbse = smb + (jt % 3) * STAGEB + KTILE;
            #pragma unroll
            for (int kk2 = 0; kk2 < 4; kk2++) {
                const uint32_t krow = vbse + (uint32_t)(kk2 * 16 + lr + kr8) * KLDB + (uint32_t)(nh8 * 2);
                #pragma unroll
                for (int ntp = 0; ntp < 8; ntp++) {
                    uint32_t r0, r1, r2, r3;
                    ldsm4t(r0, r1, r2, r3, krow + ntp * 32);
                    mma_bf16(o[2 * ntp], pa[kk2], r0, r1);
                    mma_bf16(o[2 * ntp + 1], pa[kk2], r2, r3);
                }
            }

            if (jt + 3 < 32) {
                BAR_SYNC_B(8);         // all B-warps done reading stage jt%3 V
                copy_tile(jt + 3);     // now safe to overwrite stage jt%3
            }
            cpa_commit();
        }

        BAR_SYNC(6);     // l ready

        const int b_ = bh >> 4, h = bh & 15;
        const int row0 = q0 + 16 * wb + g;
        const float inv0 = 1.0f / *(const float*)(sm + L_OFF + (16 * wb + g) * 4);
        const float inv1 = 1.0f / *(const float*)(sm + L_OFF + (16 * wb + g + 8) * 4);
        float* op0 = out + ((size_t)(b_ * S_LEN + row0)) * D_DIM + h * HD;
        float* op1 = op0 + 8 * D_DIM;
        #pragma unroll
        for (int nt = 0; nt < 16; nt++) {
            int c = nt * 8 + 2 * t;
            *(float2*)(op0 + c) = make_float2(o[nt][0] * inv0, o[nt][1] * inv0);
            *(float2*)(op1 + c) = make_float2(o[nt][2] * inv1, o[nt][3] * inv1);
        }
    }
}

// ---------------- launch ----------------
extern "C" void kernel_launch(void* const* d_in, const int* in_sizes, int n_in,
                              void* d_out, int out_size) {
    const float* x = (const float*)d_in[0];
    const float* w1 = (const float*)d_in[1];
    const float* w2 = (const float*)d_in[2];
    const float* w3 = (const float*)d_in[3];
    const float* w4 = (const float*)d_in[4];
    const float* w5 = (const float*)d_in[5];
    const float* w6 = (const float*)d_in[6];

    quant_scale_kernel<<<6, 1024>>>(w1, w2, w3, w4, w5, w6);
    quant_pack_kernel<<<dim3(8, 6), 256>>>(w1, w2, w3, w4, w5, w6);

    proj_kernel<<<NTOK, 256>>>(x);

    cudaFuncSetAttribute(attn_kernel, cudaFuncAttributeMaxDynamicSharedMemorySize, ATTN_SMEM_BYTES);
    attn_kernel<<<dim3(S_LEN / 128, BHTOT), 512, ATTN_SMEM_BYTES>>>((float*)d_out);
}

// round 13
// speedup vs baseline: 1.1812x; 1.1812x over previous
#include <cuda_runtime.h>
#include <cuda_bf16.h>
#include <math.h>
#include <stdint.h>

#define EPSQ 1e-5f
#define QBF  127.0f

#define S_LEN 2048
#define D_DIM 2048
#define P_DIM 16
#define HEADS 16
#define HD    128
#define BATCH 2
#define NTOK  (BATCH * S_LEN)
#define BHTOT (BATCH * HEADS)

// ---------------- scratch ----------------
__device__ __nv_bfloat16 g_proj[3][(size_t)BHTOT * S_LEN * HD];   // q(*log2e/sqrt(hd)),k,v
__device__ int4  g_wq[6][2048];
__device__ float g_wscale[6];
__device__ float g_winv[6];

// ---------------- weight scale (reduce only) ----------------
__global__ __launch_bounds__(1024) void quant_scale_kernel(
        const float* __restrict__ w0, const float* __restrict__ w1,
        const float* __restrict__ w2, const float* __restrict__ w3,
        const float* __restrict__ w4, const float* __restrict__ w5) {
    const float* ws[6] = {w0, w1, w2, w3, w4, w5};
    const int j = blockIdx.x;
    const float* w = ws[j];
    const int N = P_DIM * D_DIM;
    int tid = threadIdx.x;

    float sum = 0.f;
    for (int i = tid; i < N; i += 1024) sum += fabsf(w[i]);
    #pragma unroll
    for (int o = 16; o > 0; o >>= 1) sum += __shfl_xor_sync(0xffffffffu, sum, o);
    __shared__ float red[32];
    if ((tid & 31) == 0) red[tid >> 5] = sum;
    __syncthreads();
    if (tid == 0) {
        float t = 0.f;
        for (int k = 0; k < 32; k++) t += red[k];
        float sc = fmaxf(t / (float)N, EPSQ);
        g_wscale[j] = sc;
        g_winv[j] = 1.0f / sc;
    }
}

// ---------------- weight quantize ----------------
__global__ __launch_bounds__(256) void quant_pack_kernel(
        const float* __restrict__ w0, const float* __restrict__ w1,
        const float* __restrict__ w2, const float* __restrict__ w3,
        const float* __restrict__ w4, const float* __restrict__ w5) {
    const float* ws[6] = {w0, w1, w2, w3, w4, w5};
    const int j = blockIdx.y;
    const float* w = ws[j] + blockIdx.x * 4096;
    char* out = (char*)g_wq[j] + blockIdx.x * 4096;
    const float wsv = g_winv[j];
    int tid = threadIdx.x;
    #pragma unroll
    for (int u = 0; u < 4; u++) {
        int base = (tid + u * 256) * 4;
        float4 v = *(const float4*)(w + base);
        char4 q;
        float a;
        a = fminf(fmaxf(rintf(v.x * wsv), -1.f), 1.f); q.x = (char)(int)a;
        a = fminf(fmaxf(rintf(v.y * wsv), -1.f), 1.f); q.y = (char)(int)a;
        a = fminf(fmaxf(rintf(v.z * wsv), -1.f), 1.f); q.z = (char)(int)a;
        a = fminf(fmaxf(rintf(v.w * wsv), -1.f), 1.f); q.w = (char)(int)a;
        *(char4*)(out + base) = q;
    }
}

// ---------------- fused projection: one block per token, all 3 matrices ----------------
__global__ __launch_bounds__(256) void proj_kernel(const float* __restrict__ x) {
    const int t = blockIdx.x;
    const int b = t >> 11;
    const int s = t & 2047;
    const int tid = threadIdx.x;

    __shared__ float xs[D_DIM];
    __shared__ int   xq[D_DIM / 4];
    __shared__ int   redi[8 * 16];
    __shared__ float rmax[8];
    __shared__ float s_cmax;
    __shared__ int   aqp[3][4];
    __shared__ float fct[3];

    const float* xr = x + (size_t)t * D_DIM;
    float mx = 0.f;
    for (int i = tid; i < D_DIM / 4; i += 256) {
        float4 v = ((const float4*)xr)[i];
        ((float4*)xs)[i] = v;
        mx = fmaxf(mx, fmaxf(fmaxf(fabsf(v.x), fabsf(v.y)), fmaxf(fabsf(v.z), fabsf(v.w))));
    }
    #pragma unroll
    for (int o = 16; o > 0; o >>= 1) mx = fmaxf(mx, __shfl_xor_sync(0xffffffffu, mx, o));
    if ((tid & 31) == 0) rmax[tid >> 5] = mx;
    __syncthreads();
    if (tid == 0) {
        float mm = rmax[0];
        for (int k = 1; k < 8; k++) mm = fmaxf(mm, rmax[k]);
        s_cmax = fmaxf(mm, EPSQ);
    }
    __syncthreads();
    const float cmax = s_cmax;
    const float sx = QBF / cmax;

    {
        int base = tid * 8;
        #pragma unroll
        for (int g = 0; g < 2; g++) {
            int v = 0;
            #pragma unroll
            for (int u = 0; u < 4; u++) {
                float q = rintf(xs[base + g * 4 + u] * sx);
                q = fminf(fmaxf(q, -128.f), 127.f);
                v |= (((int)q) & 0xFF) << (8 * u);
            }
            xq[tid * 2 + g] = v;
        }
    }
    __syncthreads();

    const int x0 = xq[tid * 2 + 0];
    const int x1 = xq[tid * 2 + 1];

    #pragma unroll 1
    for (int m = 0; m < 3; m++) {
        const int* wmat = (const int*)g_wq[2 * m];
        int acc[16];
        #pragma unroll
        for (int p = 0; p < 16; p++) {
            const int* wp = wmat + p * 512;
            int a = __dp4a(x0, wp[tid * 2 + 0], 0);
            a = __dp4a(x1, wp[tid * 2 + 1], a);
            acc[p] = a;
        }
        #pragma unroll
        for (int p = 0; p < 16; p++) acc[p] = __reduce_add_sync(0xffffffffu, acc[p]);
        if ((tid & 31) == 0) {
            #pragma unroll
            for (int p = 0; p < 16; p++) redi[(tid >> 5) * 16 + p] = acc[p];
        }
        __syncthreads();
        if (tid < 16) {
            int tot = 0;
            #pragma unroll
            for (int w = 0; w < 8; w++) tot += redi[w * 16 + tid];
            float a = (float)tot * (cmax / QBF) * g_wscale[2 * m];
            float h = 0.5f * a * (1.0f + erff(a * 0.70710678118654752f));
            float ss = h * h;
            #pragma unroll
            for (int o = 8; o > 0; o >>= 1) ss += __shfl_xor_sync(0x0000ffffu, ss, o, 16);
            float nrm = fmaxf(sqrtf(ss), 1e-12f);
            h = h / nrm * 4.0f;
            float am = fabsf(h);
            #pragma unroll
            for (int o = 8; o > 0; o >>= 1) am = fmaxf(am, __shfl_xor_sync(0x0000ffffu, am, o, 16));
            am = fmaxf(am, EPSQ);
            float sa = QBF / am;
            float q = fminf(fmaxf(rintf(h * sa), -128.f), 127.f);
            ((char*)&aqp[m][0])[tid] = (char)(int)q;
            if (tid == 0) {
                float f = (am / QBF) * g_wscale[2 * m + 1];
                if (m == 0) f *= 0.08838834764831845f * 1.4426950408889634f; // 1/sqrt(hd)*log2(e)
                fct[m] = f;
            }
        }
        __syncthreads();
    }

    #pragma unroll
    for (int j = 0; j < 8; j++) {
        int d = tid + 256 * j;
        int h = d >> 7, dh = d & 127;
        size_t oidx = ((size_t)(b * HEADS + h) * S_LEN + s) * HD + dh;
        #pragma unroll
        for (int m = 0; m < 3; m++) {
            const int4 wv = g_wq[2 * m + 1][d];
            int acc = __dp4a(aqp[m][0], wv.x, 0);
            acc = __dp4a(aqp[m][1], wv.y, acc);
            acc = __dp4a(aqp[m][2], wv.z, acc);
            acc = __dp4a(aqp[m][3], wv.w, acc);
            g_proj[m][oidx] = __float2bfloat16((float)acc * fct[m]);
        }
    }
}

// ======= flash attention: BM=64, 128 threads, 2 CTAs/SM, ldsm-trans V =======
#define BM 64
#define KLDB  272                    // bytes per K/V smem row (128 bf16 + 16B pad)
#define KLD2  68                     // words per row
#define KTILE (64 * KLDB)            // 17408
#define STAGEB (2 * KTILE)           // 34816 (K + V, both [key64][hd128])
#define NST   3
#define ATTN_SMEM_BYTES (NST * STAGEB)   // 104448 -> 2 CTAs/SM

__device__ __forceinline__ void mma_bf16(float* d, const uint32_t* a, const uint32_t b0, const uint32_t b1) {
    asm volatile("mma.sync.aligned.m16n8k16.row.col.f32.bf16.bf16.f32 "
        "{%0,%1,%2,%3}, {%4,%5,%6,%7}, {%8,%9}, {%0,%1,%2,%3};"
        : "+f"(d[0]), "+f"(d[1]), "+f"(d[2]), "+f"(d[3])
        : "r"(a[0]), "r"(a[1]), "r"(a[2]), "r"(a[3]), "r"(b0), "r"(b1));
}
__device__ __forceinline__ void ldsm4(uint32_t& r0, uint32_t& r1, uint32_t& r2, uint32_t& r3, uint32_t addr) {
    asm volatile("ldmatrix.sync.aligned.m8n8.x4.shared.b16 {%0,%1,%2,%3}, [%4];"
        : "=r"(r0), "=r"(r1), "=r"(r2), "=r"(r3) : "r"(addr));
}
__device__ __forceinline__ void ldsm4t(uint32_t& r0, uint32_t& r1, uint32_t& r2, uint32_t& r3, uint32_t addr) {
    asm volatile("ldmatrix.sync.aligned.m8n8.x4.trans.shared.b16 {%0,%1,%2,%3}, [%4];"
        : "=r"(r0), "=r"(r1), "=r"(r2), "=r"(r3) : "r"(addr));
}
__device__ __forceinline__ uint32_t packbf(float hi, float lo) {
    uint32_t d;
    asm("cvt.rn.bf16x2.f32 %0, %1, %2;" : "=r"(d) : "f"(hi), "f"(lo));
    return d;
}
__device__ __forceinline__ float ex2(float x) {
    float y;
    asm("ex2.approx.f32 %0, %1;" : "=f"(y) : "f"(x));
    return y;
}
__device__ __forceinline__ void cpa16(uint32_t dst, const void* src) {
    asm volatile("cp.async.cg.shared.global [%0], [%1], 16;" :: "r"(dst), "l"(src));
}
__device__ __forceinline__ void cpa_commit() {
    asm volatile("cp.async.commit_group;" ::: "memory");
}
template<int N> __device__ __forceinline__ void cpa_wait() {
    asm volatile("cp.async.wait_group %0;" :: "n"(N) : "memory");
}

__global__ __launch_bounds__(128, 2) void attn_kernel(float* __restrict__ out) {
    extern __shared__ char sm[];
    const int bh = blockIdx.y;
    const int q0 = blockIdx.x * BM;
    const int tid = threadIdx.x;
    const int w = tid >> 5;            // 0..3
    const int lane = tid & 31;
    const int g = lane >> 2;
    const int t = lane & 3;
    const uint32_t smb = (uint32_t)__cvta_generic_to_shared(sm);

    // ldmatrix lane decomposition
    const int lr  = lane & 7;
    const int kr8 = 8 * ((lane >> 3) & 1);
    const int nh8 = 8 * ((lane >> 4) & 1);

    // K (non-trans) per-ntile offsets: rows are keys, 16 bytes per k-half
    uint32_t koff[4];
    #pragma unroll
    for (int ntp = 0; ntp < 4; ntp++)
        koff[ntp] = (uint32_t)((16 * ntp + nh8 + lr) * KLDB + (kr8 ? 16 : 0));

    // -------- stage Q (64 rows) through stage0 area, build A-fragments --------
    {
        const __nv_bfloat16* qb = g_proj[0] + ((size_t)bh * S_LEN + q0) * HD;
        uint4* smq = (uint4*)sm;
        for (int i = tid; i < 64 * 16; i += 128) {
            int r = i >> 4, c = i & 15;
            smq[r * 17 + c] = ((const uint4*)(qb + (size_t)r * HD))[c];
        }
    }
    __syncthreads();

    uint32_t qa[8][4];
    {
        const uint32_t* Q = (const uint32_t*)sm;
        const int r0 = (16 * w + g) * KLD2;
        const int r1 = r0 + 8 * KLD2;
        #pragma unroll
        for (int kk = 0; kk < 8; kk++) {
            int c = kk * 8 + t;
            qa[kk][0] = Q[r0 + c];
            qa[kk][1] = Q[r1 + c];
            qa[kk][2] = Q[r0 + c + 4];
            qa[kk][3] = Q[r1 + c + 4];
        }
    }
    __syncthreads();

    const __nv_bfloat16* kbase = g_proj[1] + (size_t)bh * S_LEN * HD;
    const __nv_bfloat16* vbase = g_proj[2] + (size_t)bh * S_LEN * HD;

    auto copy_tile = [&](int jt) {
        const uint32_t base = smb + (jt % 3) * STAGEB;
        const __nv_bfloat16* kb = kbase + (size_t)jt * 64 * HD;
        const __nv_bfloat16* vb = vbase + (size_t)jt * 64 * HD;
        #pragma unroll
        for (int u = 0; u < 8; u++) {
            int i = tid + u * 128;
            int r = i >> 4, c = i & 15;
            cpa16(base + r * KLDB + c * 16, kb + r * HD + c * 8);
            cpa16(base + KTILE + r * KLDB + c * 16, vb + r * HD + c * 8);
        }
    };

    copy_tile(0); cpa_commit();
    copy_tile(1); cpa_commit();

    float o[16][4];
    #pragma unroll
    for (int nt = 0; nt < 16; nt++) { o[nt][0] = 0.f; o[nt][1] = 0.f; o[nt][2] = 0.f; o[nt][3] = 0.f; }
    float m0 = -INFINITY, m1 = -INFINITY, l0 = 0.f, l1 = 0.f;

    float sA[8][4], sB[8][4];

    // prologue: S_0 (tile 0 resident after wait<1>)
    cpa_wait<1>();
    __syncthreads();
    {
        const uint32_t kb0 = smb;
        #pragma unroll
        for (int nt = 0; nt < 8; nt++) { sA[nt][0] = 0.f; sA[nt][1] = 0.f; sA[nt][2] = 0.f; sA[nt][3] = 0.f; }
        #pragma unroll
        for (int kk = 0; kk < 8; kk++) {
            #pragma unroll
            for (int ntp = 0; ntp < 4; ntp++) {
                uint32_t r0, r1, r2, r3;
                ldsm4(r0, r1, r2, r3, kb0 + koff[ntp] + kk * 32);
                mma_bf16(sA[2 * ntp], qa[kk], r0, r1);
                mma_bf16(sA[2 * ntp + 1], qa[kk], r2, r3);
            }
        }
    }

    // body: wait all pending (tile jt+1 resident), sync (protects stage (jt-1)%3),
    // prefetch jt+2, issue S(jt+1), softmax(jt), PV(jt) with trans-ldsm V
    #define ITER_BODY(SCUR, SNXT, JT)                                                     \
    {                                                                                     \
        const int jt_ = (JT);                                                             \
        cpa_wait<0>();                                                                    \
        __syncthreads();                                                                  \
        if (jt_ + 2 < 32) copy_tile(jt_ + 2);                                             \
        cpa_commit();                                                                     \
        if (jt_ < 31) {                                                                   \
            const uint32_t kbN = smb + ((jt_ + 1) % 3) * STAGEB;                          \
            _Pragma("unroll")                                                             \
            for (int nt = 0; nt < 8; nt++) {                                              \
                SNXT[nt][0] = 0.f; SNXT[nt][1] = 0.f; SNXT[nt][2] = 0.f; SNXT[nt][3] = 0.f;\
            }                                                                             \
            _Pragma("unroll")                                                             \
            for (int kk = 0; kk < 8; kk++) {                                              \
                _Pragma("unroll")                                                         \
                for (int ntp = 0; ntp < 4; ntp++) {                                       \
                    uint32_t r0, r1, r2, r3;                                              \
                    ldsm4(r0, r1, r2, r3, kbN + koff[ntp] + kk * 32);                     \
                    mma_bf16(SNXT[2 * ntp], qa[kk], r0, r1);                              \
                    mma_bf16(SNXT[2 * ntp + 1], qa[kk], r2, r3);                          \
                }                                                                         \
            }                                                                             \
        }                                                                                 \
        float mt0 = -INFINITY, mt1 = -INFINITY;                                           \
        _Pragma("unroll")                                                                 \
        for (int nt = 0; nt < 8; nt++) {                                                  \
            mt0 = fmaxf(mt0, fmaxf(SCUR[nt][0], SCUR[nt][1]));                            \
            mt1 = fmaxf(mt1, fmaxf(SCUR[nt][2], SCUR[nt][3]));                            \
        }                                                                                 \
        mt0 = fmaxf(mt0, __shfl_xor_sync(0xffffffffu, mt0, 1));                           \
        mt0 = fmaxf(mt0, __shfl_xor_sync(0xffffffffu, mt0, 2));                           \
        mt1 = fmaxf(mt1, __shfl_xor_sync(0xffffffffu, mt1, 1));                           \
        mt1 = fmaxf(mt1, __shfl_xor_sync(0xffffffffu, mt1, 2));                           \
        float mn0 = fmaxf(m0, mt0), mn1 = fmaxf(m1, mt1);                                 \
        float c0 = ex2(m0 - mn0), c1 = ex2(m1 - mn1);                                     \
        m0 = mn0; m1 = mn1;                                                               \
        float rs0 = 0.f, rs1 = 0.f;                                                       \
        _Pragma("unroll")                                                                 \
        for (int nt = 0; nt < 8; nt++) {                                                  \
            SCUR[nt][0] = ex2(SCUR[nt][0] - mn0);                                         \
            SCUR[nt][1] = ex2(SCUR[nt][1] - mn0);                                         \
            SCUR[nt][2] = ex2(SCUR[nt][2] - mn1);                                         \
            SCUR[nt][3] = ex2(SCUR[nt][3] - mn1);                                         \
            rs0 += SCUR[nt][0] + SCUR[nt][1];                                             \
            rs1 += SCUR[nt][2] + SCUR[nt][3];                                             \
        }                                                                                 \
        rs0 += __shfl_xor_sync(0xffffffffu, rs0, 1);                                      \
        rs0 += __shfl_xor_sync(0xffffffffu, rs0, 2);                                      \
        rs1 += __shfl_xor_sync(0xffffffffu, rs1, 1);                                      \
        rs1 += __shfl_xor_sync(0xffffffffu, rs1, 2);                                      \
        l0 = l0 * c0 + rs0;                                                               \
        l1 = l1 * c1 + rs1;                                                               \
        _Pragma("unroll")                                                                 \
        for (int nt = 0; nt < 16; nt++) {                                                 \
            o[nt][0] *= c0; o[nt][1] *= c0;                                               \
            o[nt][2] *= c1; o[nt][3] *= c1;                                               \
        }                                                                                 \
        uint32_t pa[4][4];                                                                \
        _Pragma("unroll")                                                                 \
        for (int kk2 = 0; kk2 < 4; kk2++) {                                               \
            const int n0 = 2 * kk2, n1 = 2 * kk2 + 1;                                     \
            pa[kk2][0] = packbf(SCUR[n0][1], SCUR[n0][0]);                                \
            pa[kk2][1] = packbf(SCUR[n0][3], SCUR[n0][2]);                                \
            pa[kk2][2] = packbf(SCUR[n1][1], SCUR[n1][0]);                                \
            pa[kk2][3] = packbf(SCUR[n1][3], SCUR[n1][2]);                                \
        }                                                                                 \
        const uint32_t vbse = smb + (jt_ % 3) * STAGEB + KTILE;                           \
        _Pragma("unroll")                                                                 \
        for (int kk2 = 0; kk2 < 4; kk2++) {                                               \
            const uint32_t krow = vbse + (uint32_t)(kk2 * 16 + lr + kr8) * KLDB           \
                                  + (uint32_t)(nh8 * 2);                                  \
            _Pragma("unroll")                                                             \
            for (int ntp = 0; ntp < 8; ntp++) {                                           \
                uint32_t r0, r1, r2, r3;                                                  \
                ldsm4t(r0, r1, r2, r3, krow + ntp * 32);                                  \
                mma_bf16(o[2 * ntp], pa[kk2], r0, r1);                                    \
                mma_bf16(o[2 * ntp + 1], pa[kk2], r2, r3);                                \
            }                                                                             \
        }                                                                                 \
    }

    #pragma unroll 1
    for (int jt = 0; jt < 32; jt += 2) {
        ITER_BODY(sA, sB, jt);
        ITER_BODY(sB, sA, jt + 1);
    }
    #undef ITER_BODY

    // -------- epilogue --------
    const int b_ = bh >> 4, h = bh & 15;
    const int row0 = q0 + 16 * w + g;
    const int row1 = row0 + 8;
    const float inv0 = 1.0f / l0;
    const float inv1 = 1.0f / l1;
    float* op0 = out + ((size_t)(b_ * S_LEN + row0)) * D_DIM + h * HD;
    float* op1 = out + ((size_t)(b_ * S_LEN + row1)) * D_DIM + h * HD;
    #pragma unroll
    for (int nt = 0; nt < 16; nt++) {
        int c = nt * 8 + 2 * t;
        *(float2*)(op0 + c) = make_float2(o[nt][0] * inv0, o[nt][1] * inv0);
        *(float2*)(op1 + c) = make_float2(o[nt][2] * inv1, o[nt][3] * inv1);
    }
}

// ---------------- launch ----------------
extern "C" void kernel_launch(void* const* d_in, const int* in_sizes, int n_in,
                              void* d_out, int out_size) {
    const float* x = (const float*)d_in[0];
    const float* w1 = (const float*)d_in[1];
    const float* w2 = (const float*)d_in[2];
    const float* w3 = (const float*)d_in[3];
    const float* w4 = (const float*)d_in[4];
    const float* w5 = (const float*)d_in[5];
    const float* w6 = (const float*)d_in[6];

    quant_scale_kernel<<<6, 1024>>>(w1, w2, w3, w4, w5, w6);
    quant_pack_kernel<<<dim3(8, 6), 256>>>(w1, w2, w3, w4, w5, w6);

    proj_kernel<<<NTOK, 256>>>(x);

    cudaFuncSetAttribute(attn_kernel, cudaFuncAttributeMaxDynamicSharedMemorySize, ATTN_SMEM_BYTES);
    attn_kernel<<<dim3(S_LEN / BM, BHTOT), 128, ATTN_SMEM_BYTES>>>((float*)d_out);
}